// round 10
// baseline (speedup 1.0000x reference)
#include <cuda_runtime.h>
#include <cuda_bf16.h>
#include <math.h>

#define HN 256
#define VN 8192
#define SN 4096
#define LDA 40          // bf16 row stride in smem tiles (80B -> ldmatrix conflict-free)
#define KC 32           // k-chunk

// ---------------- device scratch ----------------
__device__ float g_a[HN];                 // Wa*hidden + Wa_b + Ua_b
__device__ float g_w[2 * HN];             // Wz*hidden+Wzb, Wr*hidden+Wrb
__device__ float g_u[3 * HN];             // Uz*y+b, Ur*y+b, Uh*y+b
__device__ float g_expE[SN];              // exp(attention logits) (|E|<~5, no max needed)
__device__ float g_sumexp;
__device__ float g_Ci[2 * HN];
__device__ float g_zr[2 * HN];
__device__ float g_hid[HN];
__device__ float g_logits[VN];
__device__ float g_vsum;
__device__ __nv_bfloat16 g_Ua16[HN * 512];  // Ua in bf16, [h][k] row-major

__device__ __forceinline__ float warpSum(float v) {
#pragma unroll
    for (int o = 16; o; o >>= 1) v += __shfl_down_sync(0xffffffffu, v, o);
    return v;
}
__device__ __forceinline__ float blockSum256(float v, float* sred) {
    int t = threadIdx.x;
    v = warpSum(v);
    if ((t & 31) == 0) sred[t >> 5] = v;
    __syncthreads();
    float r = 0.f;
    if (t < 8) {
        r = sred[t];
#pragma unroll
        for (int o = 4; o; o >>= 1) r += __shfl_down_sync(0xffu, r, o);
    }
    return r;
}
__device__ __forceinline__ unsigned pkbf(float lo, float hi) {
    __nv_bfloat162 h(__float2bfloat16(lo), __float2bfloat16(hi));
    return *reinterpret_cast<unsigned*>(&h);
}
__device__ __forceinline__ float tanh_fast(float x) {
    float y; asm("tanh.approx.f32 %0, %1;" : "=f"(y) : "f"(x)); return y;
}
__device__ __forceinline__ void ldm_x4(unsigned& r0, unsigned& r1, unsigned& r2, unsigned& r3,
                                       unsigned addr) {
    asm volatile("ldmatrix.sync.aligned.m8n8.x4.shared.b16 {%0,%1,%2,%3}, [%4];"
                 : "=r"(r0), "=r"(r1), "=r"(r2), "=r"(r3) : "r"(addr));
}
__device__ __forceinline__ void mma_bf16(float* c, unsigned a0, unsigned a1, unsigned a2,
                                         unsigned a3, unsigned b0, unsigned b1) {
    asm volatile(
        "mma.sync.aligned.m16n8k16.row.col.f32.bf16.bf16.f32 "
        "{%0,%1,%2,%3},{%4,%5,%6,%7},{%8,%9},{%0,%1,%2,%3};"
        : "+f"(c[0]), "+f"(c[1]), "+f"(c[2]), "+f"(c[3])
        : "r"(a0), "r"(a1), "r"(a2), "r"(a3), "r"(b0), "r"(b1));
}

// ---------------- K0: g_a GEMV + init + Ua -> bf16 convert ----------------
__global__ void __launch_bounds__(256) k0(const float* __restrict__ hidden,
                                          const float* __restrict__ Waw,
                                          const float* __restrict__ Wab,
                                          const float* __restrict__ Uab,
                                          const float* __restrict__ Uaw) {
    int b = blockIdx.x, t = threadIdx.x;
    if (b < HN) {
        __shared__ float sred[8];
        float v = Waw[b * HN + t] * hidden[t];
        float r = blockSum256(v, sred);
        if (t == 0) g_a[b] = r + Wab[b] + Uab[b];
        return;
    }
    if (b == HN) {  // init
        g_Ci[t] = 0.f; g_Ci[t + HN] = 0.f;
        if (t == 0) g_sumexp = 0.f;
        if (t == 1) g_vsum = 0.f;
        return;
    }
    // Ua convert: 64 blocks x 2048 elems
    int base = (b - HN - 1) * 2048 + t * 8;
    float4 v0 = *reinterpret_cast<const float4*>(Uaw + base);
    float4 v1 = *reinterpret_cast<const float4*>(Uaw + base + 4);
    uint4 o;
    o.x = pkbf(v0.x, v0.y); o.y = pkbf(v0.z, v0.w);
    o.z = pkbf(v1.x, v1.y); o.w = pkbf(v1.z, v1.w);
    *reinterpret_cast<uint4*>(g_Ua16 + base) = o;
}

// ---------------- K_fused: blocks 0..127 attention MMA,
//                  128..895 U GEMVs, 896..1407 W GEMVs ---------------------
__global__ void __launch_bounds__(256) k_fused(
        const int* __restrict__ tok, const float* __restrict__ emb,
        const float* __restrict__ hidden, const float* __restrict__ enc,
        const float* __restrict__ Vaw, const float* __restrict__ Vab,
        const float* __restrict__ Uzw, const float* __restrict__ Uzb,
        const float* __restrict__ Urw, const float* __restrict__ Urb,
        const float* __restrict__ Uhw, const float* __restrict__ Uhb,
        const float* __restrict__ Wzw, const float* __restrict__ Wzb,
        const float* __restrict__ Wrw, const float* __restrict__ Wrb) {
    int b = blockIdx.x, t = threadIdx.x;

    if (b >= 128) {
        __shared__ float sred[8];
        if (b < 896) {
            // ---- U GEMV: g_u[g*HN+h] = U[h,:] . emb[tok] + b ----
            int idx = b - 128, g = idx >> 8, h = idx & 255;
            const float* W = (g == 0) ? Uzw : ((g == 1) ? Urw : Uhw);
            const float* B = (g == 0) ? Uzb : ((g == 1) ? Urb : Uhb);
            const float4* y = reinterpret_cast<const float4*>(emb + (size_t)tok[0] * VN);
            const float4* w = reinterpret_cast<const float4*>(W + (size_t)h * VN);
            float v = 0.f;
#pragma unroll
            for (int i = 0; i < VN / 4; i += 256) {
                float4 a = w[i + t], c = y[i + t];
                v = fmaf(a.x, c.x, fmaf(a.y, c.y, fmaf(a.z, c.z, fmaf(a.w, c.w, v))));
            }
            float r = blockSum256(v, sred);
            if (t == 0) g_u[g * HN + h] = r + B[h];
        } else {
            // ---- Wz/Wr GEMV on hidden ----
            int idx = b - 896, g = idx >> 8, h = idx & 255;
            const float* W = g ? Wrw : Wzw;
            const float* Wb = g ? Wrb : Wzb;
            float v = W[h * HN + t] * hidden[t];
            float r = blockSum256(v, sred);
            if (t == 0) g_w[g * HN + h] = r + Wb[h];
        }
        return;
    }

    // ===================== attention: 32 s-rows via bf16 MMA =====================
    __shared__ __align__(16) __nv_bfloat16 As[32 * LDA];
    __shared__ __align__(16) __nv_bfloat16 Bs[256 * LDA];
    __shared__ float sE[32];

    int s0 = b * 32;
    int lane = t & 31, wid = t >> 5;
    int sg = wid & 1;        // s-group (16 rows)
    int hg = wid >> 1;       // h-group (64 cols)

    if (t < 32) sE[t] = 0.f;

    float acc[8][4];
#pragma unroll
    for (int nt = 0; nt < 8; nt++)
#pragma unroll
        for (int j = 0; j < 4; j++) acc[nt][j] = 0.f;

    unsigned as_base = (unsigned)__cvta_generic_to_shared(As);
    unsigned bs_base = (unsigned)__cvta_generic_to_shared(Bs);
    unsigned a_addr = as_base + ((sg * 16 + (lane & 15)) * LDA + (lane >> 4) * 8) * 2;
    unsigned b_addr0 = bs_base + ((hg * 64 + (lane & 15)) * LDA + (lane >> 4) * 8) * 2;

    // staging indices
    int ar = t >> 3, akc = (t & 7) * 4;   // A: row, k-col(group of 4)

    for (int kb = 0; kb < 512; kb += KC) {
        __syncthreads();
        // stage A: enc fp32 -> bf16 (32 x 32)
        {
            float4 v = *reinterpret_cast<const float4*>(enc + (size_t)(s0 + ar) * 512 + kb + akc);
            uint2 p; p.x = pkbf(v.x, v.y); p.y = pkbf(v.z, v.w);
            *reinterpret_cast<uint2*>(As + ar * LDA + akc) = p;
        }
        // stage B: g_Ua16 row t, 32 bf16 = 64B
        {
            const uint4* src = reinterpret_cast<const uint4*>(g_Ua16 + (size_t)t * 512 + kb);
            uint4* dst = reinterpret_cast<uint4*>(Bs + t * LDA);
            dst[0] = src[0]; dst[1] = src[1]; dst[2] = src[2]; dst[3] = src[3];
        }
        __syncthreads();
#pragma unroll
        for (int ks = 0; ks < 2; ks++) {
            unsigned a0, a1, a2, a3;
            ldm_x4(a0, a1, a2, a3, a_addr + ks * 32);
#pragma unroll
            for (int ntp = 0; ntp < 4; ntp++) {
                unsigned r0, r1, r2, r3;
                ldm_x4(r0, r1, r2, r3, b_addr0 + ntp * 16 * LDA * 2 + ks * 32);
                mma_bf16(acc[2 * ntp],     a0, a1, a2, a3, r0, r2);
                mma_bf16(acc[2 * ntp + 1], a0, a1, a2, a3, r1, r3);
            }
        }
    }

    // epilogue: E[s] partials = sum_h Va[h]*tanh(P + g_a[h])
    {
        int g = lane >> 2, tig = lane & 3;
        float p0 = 0.f, p1 = 0.f;
#pragma unroll
        for (int nt = 0; nt < 8; nt++) {
            int c0 = hg * 64 + nt * 8 + 2 * tig;
            float ga0 = g_a[c0], ga1 = g_a[c0 + 1];
            float va0 = Vaw[c0], va1 = Vaw[c0 + 1];
            p0 += va0 * tanh_fast(acc[nt][0] + ga0) + va1 * tanh_fast(acc[nt][1] + ga1);
            p1 += va0 * tanh_fast(acc[nt][2] + ga0) + va1 * tanh_fast(acc[nt][3] + ga1);
        }
        p0 += __shfl_xor_sync(0xffffffffu, p0, 1); p0 += __shfl_xor_sync(0xffffffffu, p0, 2);
        p1 += __shfl_xor_sync(0xffffffffu, p1, 1); p1 += __shfl_xor_sync(0xffffffffu, p1, 2);
        if (tig == 0) {
            atomicAdd(&sE[sg * 16 + g], p0);
            atomicAdd(&sE[sg * 16 + g + 8], p1);
        }
    }
    __syncthreads();
    float ex = 0.f;
    if (t < 32) {
        ex = expf(sE[t] + Vab[0]);
        g_expE[s0 + t] = ex;
    }
    if (wid == 0) {
        float v = warpSum(ex);
        if (lane == 0) atomicAdd(&g_sumexp, v);
    }
}

// ---------------- K_ci: aij = expE/sum; Ci = sum_s aij*enc[s] -------------
__global__ void __launch_bounds__(512) k_ci(const float* __restrict__ enc,
                                            float* __restrict__ aij) {
    __shared__ float sa[16];
    int t = threadIdx.x, s0 = blockIdx.x * 16;
    float inv = 1.0f / g_sumexp;
    if (t < 16) {
        float a = g_expE[s0 + t] * inv;
        sa[t] = a;
        aij[s0 + t] = a;
    }
    __syncthreads();
    float p = 0.f;
#pragma unroll
    for (int i = 0; i < 16; i++)
        p = fmaf(sa[i], enc[(size_t)(s0 + i) * 512 + t], p);
    atomicAdd(&g_Ci[t], p);
}

// ---------------- K_zr: warp-per-row z,r gates ----------------------------
__global__ void __launch_bounds__(256) k_zr(const float* __restrict__ Czw, const float* __restrict__ Czb,
                                            const float* __restrict__ Crw, const float* __restrict__ Crb) {
    int t = threadIdx.x, lane = t & 31, wid = t >> 5;
    int row = blockIdx.x * 8 + wid;          // 0..511
    int g = row >> 8, h = row & 255;
    const float* C  = g ? Crw : Czw;
    const float* Cb = g ? Crb : Czb;
    const float4* c4  = reinterpret_cast<const float4*>(C + (size_t)h * 512);
    const float4* ci4 = reinterpret_cast<const float4*>(g_Ci);
    float v = 0.f;
#pragma unroll
    for (int j = 0; j < 4; j++) {
        float4 a = c4[lane + 32 * j], c = ci4[lane + 32 * j];
        v = fmaf(a.x, c.x, fmaf(a.y, c.y, fmaf(a.z, c.z, fmaf(a.w, c.w, v))));
    }
    v = warpSum(v);
    if (lane == 0) {
        float x = v + g_w[row] + g_u[row] + Cb[h];
        g_zr[row] = 1.f / (1.f + expf(-x));
    }
}

// ---------------- K_c: warp-per-row candidate + hidden_new -----------------
__global__ void __launch_bounds__(256) k_c(const float* __restrict__ hidden,
                                           const float* __restrict__ Whw, const float* __restrict__ Whb,
                                           const float* __restrict__ Chw, const float* __restrict__ Chb,
                                           float* __restrict__ out_hidden) {
    int t = threadIdx.x, lane = t & 31, wid = t >> 5;
    int h = blockIdx.x * 8 + wid;            // 0..255
    const float4* wh4 = reinterpret_cast<const float4*>(Whw + (size_t)h * 256);
    const float4* ch4 = reinterpret_cast<const float4*>(Chw + (size_t)h * 512);
    const float4* zr4 = reinterpret_cast<const float4*>(g_zr);
    const float4* hh4 = reinterpret_cast<const float4*>(hidden);
    const float4* ci4 = reinterpret_cast<const float4*>(g_Ci);
    float v = 0.f;
#pragma unroll
    for (int j = 0; j < 2; j++) {
        float4 a = wh4[lane + 32 * j];
        float4 r = zr4[64 + lane + 32 * j];  // g_zr[256..511]
        float4 hh = hh4[lane + 32 * j];
        v = fmaf(a.x, r.x * hh.x, fmaf(a.y, r.y * hh.y,
            fmaf(a.z, r.z * hh.z, fmaf(a.w, r.w * hh.w, v))));
    }
#pragma unroll
    for (int j = 0; j < 4; j++) {
        float4 a = ch4[lane + 32 * j], c = ci4[lane + 32 * j];
        v = fmaf(a.x, c.x, fmaf(a.y, c.y, fmaf(a.z, c.z, fmaf(a.w, c.w, v))));
    }
    v = warpSum(v);
    if (lane == 0) {
        float c = tanhf(v + g_u[2 * HN + h] + Whb[h] + Chb[h]);
        float z = g_zr[h];
        float hn = (1.f - z) * c + z * hidden[h];
        g_hid[h] = hn;
        out_hidden[h] = hn;
    }
}

// ---------------- K_v: logits + sum(exp(logits)) ---------------------------
__global__ void __launch_bounds__(256) k_v(const float* __restrict__ Vw,
                                           const float* __restrict__ Vb) {
    __shared__ __align__(16) float sh[HN];
    __shared__ float sex[8];
    int t = threadIdx.x;
    sh[t] = g_hid[t];
    __syncthreads();
    int wid = t >> 5, lane = t & 31;
    int o = blockIdx.x * 8 + wid;
    const float4* w  = reinterpret_cast<const float4*>(Vw + (size_t)o * HN);
    const float4* hv = reinterpret_cast<const float4*>(sh);
    float4 w0 = w[lane], h0 = hv[lane], w1 = w[lane + 32], h1 = hv[lane + 32];
    float v = w0.x * h0.x + w0.y * h0.y + w0.z * h0.z + w0.w * h0.w
            + w1.x * h1.x + w1.y * h1.y + w1.z * h1.z + w1.w * h1.w;
    v = warpSum(v);
    if (lane == 0) {
        float l = v + Vb[o];
        g_logits[o] = l;
        sex[wid] = expf(l);                  // |logit| small: no max needed
    }
    __syncthreads();
    if (t == 0) {
        float s = sex[0] + sex[1] + sex[2] + sex[3] + sex[4] + sex[5] + sex[6] + sex[7];
        atomicAdd(&g_vsum, s);
    }
}

// ---------------- K_out ----------------------------------------------------
__global__ void __launch_bounds__(256) k_out(float* __restrict__ out) {
    __shared__ float lse;
    int t = threadIdx.x;
    if (t == 0) lse = logf(g_vsum);
    __syncthreads();
    int i = blockIdx.x * 256 + t;
    out[i] = g_logits[i] - lse;
}

// ---------------------------------------------------------------------------
extern "C" void kernel_launch(void* const* d_in, const int* in_sizes, int n_in,
                              void* d_out, int out_size) {
    (void)in_sizes; (void)n_in; (void)out_size;
    const int*   tok    = (const int*)  d_in[0];
    const float* hidden = (const float*)d_in[1];
    const float* enc    = (const float*)d_in[2];
    const float* emb    = (const float*)d_in[3];
    const float *Uzw = (const float*)d_in[4],  *Uzb = (const float*)d_in[5];
    const float *Wzw = (const float*)d_in[6],  *Wzb = (const float*)d_in[7];
    const float *Czw = (const float*)d_in[8],  *Czb = (const float*)d_in[9];
    const float *Urw = (const float*)d_in[10], *Urb = (const float*)d_in[11];
    const float *Wrw = (const float*)d_in[12], *Wrb = (const float*)d_in[13];
    const float *Crw = (const float*)d_in[14], *Crb = (const float*)d_in[15];
    const float *Uhw = (const float*)d_in[16], *Uhb = (const float*)d_in[17];
    const float *Whw = (const float*)d_in[18], *Whb = (const float*)d_in[19];
    const float *Chw = (const float*)d_in[20], *Chb = (const float*)d_in[21];
    const float *Uaw = (const float*)d_in[22], *Uab = (const float*)d_in[23];
    const float *Waw = (const float*)d_in[24], *Wab = (const float*)d_in[25];
    const float *Vaw = (const float*)d_in[26], *Vab = (const float*)d_in[27];
    const float *Vw  = (const float*)d_in[28], *Vb  = (const float*)d_in[29];

    float* out        = (float*)d_out;       // [VN] log_softmax
    float* out_hidden = out + VN;            // [HN] hidden_new
    float* aij        = out + VN + HN;       // [SN] attention weights

    k0<<<HN + 1 + 64, 256>>>(hidden, Waw, Wab, Uab, Uaw);
    k_fused<<<1408, 256>>>(tok, emb, hidden, enc, Vaw, Vab,
                           Uzw, Uzb, Urw, Urb, Uhw, Uhb,
                           Wzw, Wzb, Wrw, Wrb);
    k_ci<<<SN / 16, 512>>>(enc, aij);
    k_zr<<<64, 256>>>(Czw, Czb, Crw, Crb);
    k_c<<<32, 256>>>(hidden, Whw, Whb, Chw, Chb, out_hidden);
    k_v<<<VN / 8, 256>>>(Vw, Vb);
    k_out<<<VN / 256, 256>>>(out);
}

// round 11
// speedup vs baseline: 1.1511x; 1.1511x over previous
#include <cuda_runtime.h>
#include <cuda_bf16.h>
#include <math.h>

#define HN 256
#define VN 8192
#define SN 4096
#define LDA 40          // bf16 row stride in smem tiles (80B -> ldmatrix conflict-free)
#define KC 32           // k-chunk
#define GRID 148        // <= SM count: all CTAs resident -> grid barrier is safe

// ---------------- device scratch ----------------
__device__ float g_a[HN];                 // Wa*hidden + Wa_b + Ua_b
__device__ float g_u[3 * HN];             // Uz*y+b, Ur*y+b, Uh*y+b
__device__ float g_expE[SN];              // exp(attention logits) (|E|<~5, no max needed)
__device__ float g_sumexp;
__device__ float g_Ci[2 * HN];            // UNNORMALIZED context: scaled by 1/sumexp at use
__device__ float g_zr[2 * HN];
__device__ float g_hid[HN];
__device__ float g_logits[VN];
__device__ float g_vsum;
__device__ int   g_bar;                   // grid barrier counter (reset in k_pre)
__device__ int   g_ticket;                // work-pool ticket   (reset in k_pre)
__device__ __nv_bfloat16 g_Ua16[HN * 512];

__device__ __forceinline__ float warpSum(float v) {
#pragma unroll
    for (int o = 16; o; o >>= 1) v += __shfl_down_sync(0xffffffffu, v, o);
    return v;
}
__device__ __forceinline__ float blockSum256(float v, float* sred) {
    int t = threadIdx.x;
    v = warpSum(v);
    if ((t & 31) == 0) sred[t >> 5] = v;
    __syncthreads();
    float r = 0.f;
    if (t < 8) {
        r = sred[t];
#pragma unroll
        for (int o = 4; o; o >>= 1) r += __shfl_down_sync(0xffu, r, o);
    }
    return r;
}
__device__ __forceinline__ unsigned pkbf(float lo, float hi) {
    __nv_bfloat162 h(__float2bfloat16(lo), __float2bfloat16(hi));
    return *reinterpret_cast<unsigned*>(&h);
}
__device__ __forceinline__ float tanh_fast(float x) {
    float y; asm("tanh.approx.f32 %0, %1;" : "=f"(y) : "f"(x)); return y;
}
__device__ __forceinline__ void ldm_x4(unsigned& r0, unsigned& r1, unsigned& r2, unsigned& r3,
                                       unsigned addr) {
    asm volatile("ldmatrix.sync.aligned.m8n8.x4.shared.b16 {%0,%1,%2,%3}, [%4];"
                 : "=r"(r0), "=r"(r1), "=r"(r2), "=r"(r3) : "r"(addr));
}
__device__ __forceinline__ void mma_bf16(float* c, unsigned a0, unsigned a1, unsigned a2,
                                         unsigned a3, unsigned b0, unsigned b1) {
    asm volatile(
        "mma.sync.aligned.m16n8k16.row.col.f32.bf16.bf16.f32 "
        "{%0,%1,%2,%3},{%4,%5,%6,%7},{%8,%9},{%0,%1,%2,%3};"
        : "+f"(c[0]), "+f"(c[1]), "+f"(c[2]), "+f"(c[3])
        : "r"(a0), "r"(a1), "r"(a2), "r"(a3), "r"(b0), "r"(b1));
}
__device__ __forceinline__ void gsync(int target) {
    __syncthreads();
    if (threadIdx.x == 0) {
        __threadfence();
        atomicAdd(&g_bar, 1);
        int v;
        do {
            asm volatile("ld.acquire.gpu.b32 %0, [%1];" : "=r"(v) : "l"(&g_bar) : "memory");
        } while (v < target);
    }
    __syncthreads();
}
__device__ __forceinline__ void pf_l2(const void* p) {
    asm volatile("prefetch.global.L2 [%0];" :: "l"(p));
}
__device__ __forceinline__ void pf_range(const char* base, size_t total, int bid, int t) {
    size_t per = (((total + GRID - 1) / GRID) + 127) & ~(size_t)127;
    size_t s = (size_t)bid * per;
    size_t e = s + per; if (e > total) e = total;
    for (size_t o = s + (size_t)t * 128; o < e; o += 256u * 128u) pf_l2(base + o);
}

// ---------------- K_pre: init + Wa GEMV (warp-per-row) + Ua->bf16 ----------
__global__ void __launch_bounds__(256) k_pre(const float* __restrict__ hidden,
                                             const float* __restrict__ Waw,
                                             const float* __restrict__ Wab,
                                             const float* __restrict__ Uab,
                                             const float* __restrict__ Uaw) {
    int b = blockIdx.x, t = threadIdx.x;
    int lane = t & 31, wid = t >> 5;

    if (b == 0) {  // init scratch
        g_Ci[t] = 0.f; g_Ci[t + HN] = 0.f;
        if (t == 0) { g_sumexp = 0.f; g_vsum = 0.f; g_bar = 0; g_ticket = 0; }
    }

    // Ua convert: 64 blocks x 2048 elems
    {
        int base = b * 2048 + t * 8;
        float4 v0 = *reinterpret_cast<const float4*>(Uaw + base);
        float4 v1 = *reinterpret_cast<const float4*>(Uaw + base + 4);
        uint4 o;
        o.x = pkbf(v0.x, v0.y); o.y = pkbf(v0.z, v0.w);
        o.z = pkbf(v1.x, v1.y); o.w = pkbf(v1.z, v1.w);
        *reinterpret_cast<uint4*>(g_Ua16 + base) = o;
    }

    // Wa GEMV: warp per row, rows 0..255 over 512 warps
    int row = b * 8 + wid;
    if (row < HN) {
        const float4* w4 = reinterpret_cast<const float4*>(Waw + (size_t)row * HN);
        const float4* h4 = reinterpret_cast<const float4*>(hidden);
        float4 a0 = w4[lane], b0 = h4[lane], a1 = w4[lane + 32], b1 = h4[lane + 32];
        float v = a0.x * b0.x + a0.y * b0.y + a0.z * b0.z + a0.w * b0.w
                + a1.x * b1.x + a1.y * b1.y + a1.z * b1.z + a1.w * b1.w;
        v = warpSum(v);
        if (lane == 0) g_a[row] = v + Wab[row] + Uab[row];
    }
}

// ---------------- K_mega: persistent kernel, everything else ----------------
__global__ void __launch_bounds__(256) k_mega(
        const int* __restrict__ tok, const float* __restrict__ emb,
        const float* __restrict__ hidden, const float* __restrict__ enc,
        const float* __restrict__ Vaw, const float* __restrict__ Vab,
        const float* __restrict__ Uzw, const float* __restrict__ Uzb,
        const float* __restrict__ Urw, const float* __restrict__ Urb,
        const float* __restrict__ Uhw, const float* __restrict__ Uhb,
        const float* __restrict__ Wzw, const float* __restrict__ Wzb,
        const float* __restrict__ Wrw, const float* __restrict__ Wrb,
        const float* __restrict__ Czw, const float* __restrict__ Czb,
        const float* __restrict__ Crw, const float* __restrict__ Crb,
        const float* __restrict__ Whw, const float* __restrict__ Whb,
        const float* __restrict__ Chw, const float* __restrict__ Chb,
        const float* __restrict__ Vw,  const float* __restrict__ Vb,
        float* __restrict__ out, float* __restrict__ out_hidden,
        float* __restrict__ aij) {
    __shared__ __align__(16) __nv_bfloat16 As[32 * LDA];
    __shared__ __align__(16) __nv_bfloat16 Bs[256 * LDA];
    __shared__ float sE[32];
    __shared__ float s_ex[32];
    __shared__ float sred[8];
    __shared__ int   s_ticket;
    __shared__ __align__(16) float sh2[HN];
    __shared__ float s_vsum;

    int bid = blockIdx.x, t = threadIdx.x;
    int lane = t & 31, wid = t >> 5;

    // ======================= PHASE A: ticket work pool =======================
    // tickets 0..127: attention tiles (32 s-rows)   128..895: U-GEMV rows
    for (;;) {
        __syncthreads();
        if (t == 0) s_ticket = atomicAdd(&g_ticket, 1);
        __syncthreads();
        int w = s_ticket;
        if (w >= 896) break;

        if (w >= 128) {
            // ---- U GEMV: g_u[g*HN+h] = U[h,:] . emb[tok] + b ----
            int idx = w - 128, g = idx >> 8, h = idx & 255;
            const float* W = (g == 0) ? Uzw : ((g == 1) ? Urw : Uhw);
            const float* B = (g == 0) ? Uzb : ((g == 1) ? Urb : Uhb);
            const float4* y = reinterpret_cast<const float4*>(emb + (size_t)tok[0] * VN);
            const float4* wv = reinterpret_cast<const float4*>(W + (size_t)h * VN);
            float v = 0.f;
#pragma unroll
            for (int i = 0; i < VN / 4; i += 256) {
                float4 a = wv[i + t], c = y[i + t];
                v = fmaf(a.x, c.x, fmaf(a.y, c.y, fmaf(a.z, c.z, fmaf(a.w, c.w, v))));
            }
            float r = blockSum256(v, sred);
            if (t == 0) g_u[g * HN + h] = r + B[h];
            continue;
        }

        // ---- attention tile: 32 s-rows via bf16 MMA (+ unnormalized Ci partial)
        int s0 = w * 32;
        int sg = wid & 1;        // s-group (16 rows)
        int hg = wid >> 1;       // h-group (64 cols)
        if (t < 32) sE[t] = 0.f;

        float acc[8][4];
#pragma unroll
        for (int nt = 0; nt < 8; nt++)
#pragma unroll
            for (int j = 0; j < 4; j++) acc[nt][j] = 0.f;

        unsigned as_base = (unsigned)__cvta_generic_to_shared(As);
        unsigned bs_base = (unsigned)__cvta_generic_to_shared(Bs);
        unsigned a_addr = as_base + ((sg * 16 + (lane & 15)) * LDA + (lane >> 4) * 8) * 2;
        unsigned b_addr0 = bs_base + ((hg * 64 + (lane & 15)) * LDA + (lane >> 4) * 8) * 2;
        int ar = t >> 3, akc = (t & 7) * 4;

        for (int kb = 0; kb < 512; kb += KC) {
            __syncthreads();
            {   // stage A: enc fp32 -> bf16 (32 x 32)
                float4 v = *reinterpret_cast<const float4*>(enc + (size_t)(s0 + ar) * 512 + kb + akc);
                uint2 p; p.x = pkbf(v.x, v.y); p.y = pkbf(v.z, v.w);
                *reinterpret_cast<uint2*>(As + ar * LDA + akc) = p;
            }
            {   // stage B: g_Ua16 row t, 32 bf16 = 64B
                const uint4* src = reinterpret_cast<const uint4*>(g_Ua16 + (size_t)t * 512 + kb);
                uint4* dst = reinterpret_cast<uint4*>(Bs + t * LDA);
                dst[0] = src[0]; dst[1] = src[1]; dst[2] = src[2]; dst[3] = src[3];
            }
            __syncthreads();
#pragma unroll
            for (int ks = 0; ks < 2; ks++) {
                unsigned a0, a1, a2, a3;
                ldm_x4(a0, a1, a2, a3, a_addr + ks * 32);
#pragma unroll
                for (int ntp = 0; ntp < 4; ntp++) {
                    unsigned r0, r1, r2, r3;
                    ldm_x4(r0, r1, r2, r3, b_addr0 + ntp * 16 * LDA * 2 + ks * 32);
                    mma_bf16(acc[2 * ntp],     a0, a1, a2, a3, r0, r2);
                    mma_bf16(acc[2 * ntp + 1], a0, a1, a2, a3, r1, r3);
                }
            }
        }

        {   // epilogue: E[s] partials = sum_h Va[h]*tanh(P + g_a[h])
            int g = lane >> 2, tig = lane & 3;
            float p0 = 0.f, p1 = 0.f;
#pragma unroll
            for (int nt = 0; nt < 8; nt++) {
                int c0 = hg * 64 + nt * 8 + 2 * tig;
                float ga0 = g_a[c0], ga1 = g_a[c0 + 1];
                float va0 = Vaw[c0], va1 = Vaw[c0 + 1];
                p0 += va0 * tanh_fast(acc[nt][0] + ga0) + va1 * tanh_fast(acc[nt][1] + ga1);
                p1 += va0 * tanh_fast(acc[nt][2] + ga0) + va1 * tanh_fast(acc[nt][3] + ga1);
            }
            p0 += __shfl_xor_sync(0xffffffffu, p0, 1); p0 += __shfl_xor_sync(0xffffffffu, p0, 2);
            p1 += __shfl_xor_sync(0xffffffffu, p1, 1); p1 += __shfl_xor_sync(0xffffffffu, p1, 2);
            if (tig == 0) {
                atomicAdd(&sE[sg * 16 + g], p0);
                atomicAdd(&sE[sg * 16 + g + 8], p1);
            }
        }
        __syncthreads();
        float ex = 0.f;
        if (t < 32) {
            ex = expf(sE[t] + Vab[0]);          // |E| <~ 5: no max needed
            g_expE[s0 + t] = ex;
            s_ex[t] = ex;
        }
        if (wid == 0) {
            float v = warpSum(ex);
            if (lane == 0) atomicAdd(&g_sumexp, v);
        }
        __syncthreads();
        {   // unnormalized Ci partial: thread t handles cols t and t+256
            const float* ep = enc + (size_t)s0 * 512;
            float a0 = 0.f, a1 = 0.f;
#pragma unroll 8
            for (int i = 0; i < 32; i++) {
                float e = s_ex[i];
                a0 = fmaf(e, ep[(size_t)i * 512 + t], a0);
                a1 = fmaf(e, ep[(size_t)i * 512 + 256 + t], a1);
            }
            atomicAdd(&g_Ci[t], a0);
            atomicAdd(&g_Ci[t + 256], a1);
        }
    }

    // prefetch phase C/D/E weights into L2 while stragglers finish
    pf_range((const char*)Vw,  (size_t)VN * HN * 4, bid, t);
    pf_range((const char*)Czw, (size_t)HN * 512 * 4, bid, t);
    pf_range((const char*)Crw, (size_t)HN * 512 * 4, bid, t);
    pf_range((const char*)Chw, (size_t)HN * 512 * 4, bid, t);
    pf_range((const char*)Whw, (size_t)HN * HN * 4, bid, t);
    pf_range((const char*)Wzw, (size_t)HN * HN * 4, bid, t);
    pf_range((const char*)Wrw, (size_t)HN * HN * 4, bid, t);

    gsync(1 * GRID);

    // ======================= PHASE C: z,r gates + aij ========================
    float inv = 1.0f / g_sumexp;
    {
        int gw = bid * 8 + wid;                  // warp per row, rows 0..511
        if (gw < 2 * HN) {
            int g = gw >> 8, h = gw & 255;
            const float* C  = g ? Crw : Czw;
            const float* Cb = g ? Crb : Czb;
            const float* W  = g ? Wrw : Wzw;
            const float* Wb = g ? Wrb : Wzb;
            const float4* c4  = reinterpret_cast<const float4*>(C + (size_t)h * 512);
            const float4* ci4 = reinterpret_cast<const float4*>(g_Ci);
            float vc = 0.f;
#pragma unroll
            for (int j = 0; j < 4; j++) {
                float4 a = c4[lane + 32 * j], c = ci4[lane + 32 * j];
                vc = fmaf(a.x, c.x, fmaf(a.y, c.y, fmaf(a.z, c.z, fmaf(a.w, c.w, vc))));
            }
            const float4* w4 = reinterpret_cast<const float4*>(W + (size_t)h * HN);
            const float4* h4 = reinterpret_cast<const float4*>(hidden);
            float vw = 0.f;
#pragma unroll
            for (int j = 0; j < 2; j++) {
                float4 a = w4[lane + 32 * j], c = h4[lane + 32 * j];
                vw = fmaf(a.x, c.x, fmaf(a.y, c.y, fmaf(a.z, c.z, fmaf(a.w, c.w, vw))));
            }
            float v = warpSum(vc * inv + vw);
            if (lane == 0) {
                float x = v + g_u[gw] + Cb[h] + Wb[h];
                g_zr[gw] = 1.f / (1.f + expf(-x));
            }
        }
        int idx = bid * 256 + t;                 // aij = expE / sumexp
        if (idx < SN) aij[idx] = g_expE[idx] * inv;
    }
    gsync(2 * GRID);

    // ======================= PHASE D: candidate + hidden_new =================
    {
        int h = bid * 8 + wid;                   // warp per row, rows 0..255
        if (h < HN) {
            const float4* wh4 = reinterpret_cast<const float4*>(Whw + (size_t)h * HN);
            const float4* ch4 = reinterpret_cast<const float4*>(Chw + (size_t)h * 512);
            const float4* zr4 = reinterpret_cast<const float4*>(g_zr);
            const float4* hh4 = reinterpret_cast<const float4*>(hidden);
            const float4* ci4 = reinterpret_cast<const float4*>(g_Ci);
            float vw = 0.f, vc = 0.f;
#pragma unroll
            for (int j = 0; j < 2; j++) {
                float4 a = wh4[lane + 32 * j];
                float4 r = zr4[64 + lane + 32 * j];   // r gate = g_zr[256..511]
                float4 hh = hh4[lane + 32 * j];
                vw = fmaf(a.x, r.x * hh.x, fmaf(a.y, r.y * hh.y,
                     fmaf(a.z, r.z * hh.z, fmaf(a.w, r.w * hh.w, vw))));
            }
#pragma unroll
            for (int j = 0; j < 4; j++) {
                float4 a = ch4[lane + 32 * j], c = ci4[lane + 32 * j];
                vc = fmaf(a.x, c.x, fmaf(a.y, c.y, fmaf(a.z, c.z, fmaf(a.w, c.w, vc))));
            }
            float v = warpSum(vw + vc * inv);
            if (lane == 0) {
                float c = tanhf(v + g_u[2 * HN + h] + Whb[h] + Chb[h]);
                float z = g_zr[h];
                float hn = (1.f - z) * c + z * hidden[h];
                g_hid[h] = hn;
                out_hidden[h] = hn;
            }
        }
    }
    gsync(3 * GRID);

    // ======================= PHASE E: vocab logits + vsum ====================
    sh2[t] = g_hid[t];
    if (t == 0) s_vsum = 0.f;
    __syncthreads();
    for (int row = bid * 8 + wid; row < VN; row += GRID * 8) {
        const float4* w  = reinterpret_cast<const float4*>(Vw + (size_t)row * HN);
        const float4* hv = reinterpret_cast<const float4*>(sh2);
        float4 w0 = w[lane], h0 = hv[lane], w1 = w[lane + 32], h1 = hv[lane + 32];
        float v = w0.x * h0.x + w0.y * h0.y + w0.z * h0.z + w0.w * h0.w
                + w1.x * h1.x + w1.y * h1.y + w1.z * h1.z + w1.w * h1.w;
        v = warpSum(v);
        if (lane == 0) {
            float l = v + Vb[row];
            g_logits[row] = l;
            atomicAdd(&s_vsum, expf(l));         // |logit| small: no max needed
        }
    }
    __syncthreads();
    if (t == 0) atomicAdd(&g_vsum, s_vsum);
    gsync(4 * GRID);

    // ======================= PHASE F: out = logits - lse =====================
    {
        float lse = logf(g_vsum);
        int i = bid * 256 + t;
        if (i < VN) out[i] = g_logits[i] - lse;
    }
}

// ---------------------------------------------------------------------------
extern "C" void kernel_launch(void* const* d_in, const int* in_sizes, int n_in,
                              void* d_out, int out_size) {
    (void)in_sizes; (void)n_in; (void)out_size;
    const int*   tok    = (const int*)  d_in[0];
    const float* hidden = (const float*)d_in[1];
    const float* enc    = (const float*)d_in[2];
    const float* emb    = (const float*)d_in[3];
    const float *Uzw = (const float*)d_in[4],  *Uzb = (const float*)d_in[5];
    const float *Wzw = (const float*)d_in[6],  *Wzb = (const float*)d_in[7];
    const float *Czw = (const float*)d_in[8],  *Czb = (const float*)d_in[9];
    const float *Urw = (const float*)d_in[10], *Urb = (const float*)d_in[11];
    const float *Wrw = (const float*)d_in[12], *Wrb = (const float*)d_in[13];
    const float *Crw = (const float*)d_in[14], *Crb = (const float*)d_in[15];
    const float *Uhw = (const float*)d_in[16], *Uhb = (const float*)d_in[17];
    const float *Whw = (const float*)d_in[18], *Whb = (const float*)d_in[19];
    const float *Chw = (const float*)d_in[20], *Chb = (const float*)d_in[21];
    const float *Uaw = (const float*)d_in[22], *Uab = (const float*)d_in[23];
    const float *Waw = (const float*)d_in[24], *Wab = (const float*)d_in[25];
    const float *Vaw = (const float*)d_in[26], *Vab = (const float*)d_in[27];
    const float *Vw  = (const float*)d_in[28], *Vb  = (const float*)d_in[29];

    float* out        = (float*)d_out;       // [VN] log_softmax
    float* out_hidden = out + VN;            // [HN] hidden_new
    float* aij        = out + VN + HN;       // [SN] attention weights

    k_pre<<<64, 256>>>(hidden, Waw, Wab, Uab, Uaw);
    k_mega<<<GRID, 256>>>(tok, emb, hidden, enc, Vaw, Vab,
                          Uzw, Uzb, Urw, Urb, Uhw, Uhb,
                          Wzw, Wzb, Wrw, Wrb,
                          Czw, Czb, Crw, Crb,
                          Whw, Whb, Chw, Chb,
                          Vw, Vb, out, out_hidden, aij);
}